// round 4
// baseline (speedup 1.0000x reference)
#include <cuda_runtime.h>
#include <cuda_bf16.h>
#include <math.h>

#define N_NODES 50000
#define N_EDGES 1600000
#define IN_DIM  128
#define HID     64
#define EPS     1e-6f

// ---------------- scratch (no allocations allowed) ----------------
__device__ int   g_is64;                 // 1 if edge_index is int64, 0 if int32
__device__ int   g_deg[N_NODES];
__device__ int   g_rowptr[N_NODES + 1];
__device__ int   g_cursor[N_NODES];
__device__ float g_invdeg[N_NODES];
__device__ int   g_csr_src[N_EDGES];

__device__ float g_s[N_NODES * HID];
__device__ float g_t[N_NODES * HID];
__device__ float g_hA[N_NODES * HID];
__device__ float g_hB[N_NODES * HID];

// ---------------- edge dtype detection ----------------
// JAX with default x64-disabled silently downgrades jnp.int64 -> int32, so the
// edge buffer may be either. Valid node ids are < 50000; interpret the first
// 256 entries as int64 — if all are in range it's genuinely int64 (false
// positive probability ~(1/50000)^256), else int32.
__global__ void detect_dtype_kernel(const void* __restrict__ ei) {
    if (threadIdx.x == 0 && blockIdx.x == 0) {
        const long long* p = (const long long*)ei;
        int is64 = 1;
        for (int i = 0; i < 256; ++i) {
            long long v = p[i];
            if (v < 0 || v >= (long long)N_NODES) { is64 = 0; break; }
        }
        g_is64 = is64;
    }
}

__device__ __forceinline__ int edge_at(const void* __restrict__ ei, int idx, int is64) {
    if (is64) return (int)((const long long*)ei)[idx];
    return ((const int*)ei)[idx];
}

// ---------------- CSR build ----------------
__global__ void zero_deg_kernel() {
    int i = blockIdx.x * blockDim.x + threadIdx.x;
    if (i < N_NODES) g_deg[i] = 0;
}

__global__ void count_deg_kernel(const void* __restrict__ ei) {
    int e = blockIdx.x * blockDim.x + threadIdx.x;
    int is64 = g_is64;
    if (e < N_EDGES) {
        int dst = edge_at(ei, N_EDGES + e, is64);
        atomicAdd(&g_deg[dst], 1);
    }
}

// single-block scan over 50000 degrees -> rowptr, cursor, inv_deg
__global__ void scan_kernel() {
    __shared__ int sh[1024];
    int tid = threadIdx.x;
    int carry = 0;
    for (int base = 0; base < N_NODES; base += 1024) {
        int idx = base + tid;
        int d = (idx < N_NODES) ? g_deg[idx] : 0;
        sh[tid] = d;
        __syncthreads();
        int v = d;
        for (int off = 1; off < 1024; off <<= 1) {
            int add = (tid >= off) ? sh[tid - off] : 0;
            __syncthreads();
            v += add;
            sh[tid] = v;
            __syncthreads();
        }
        int excl = v - d;
        if (idx < N_NODES) {
            int rp = carry + excl;
            g_rowptr[idx] = rp;
            g_cursor[idx] = rp;
            g_invdeg[idx] = 1.0f / (float)max(d, 1);
        }
        __syncthreads();
        carry += sh[1023];
        __syncthreads();
    }
    if (tid == 0) g_rowptr[N_NODES] = carry;
}

__global__ void fill_csr_kernel(const void* __restrict__ ei) {
    int e = blockIdx.x * blockDim.x + threadIdx.x;
    int is64 = g_is64;
    if (e < N_EDGES) {
        int src = edge_at(ei, e, is64);
        int dst = edge_at(ei, N_EDGES + e, is64);
        int pos = atomicAdd(&g_cursor[dst], 1);
        g_csr_src[pos] = src;
    }
}

// ---------------- dual GEMM: s = h@ws, t = h@wn  ([N,DIN] x [DIN,64]) ----------------
// 256 threads: tx = output col (0..63), ty = node-in-group (0..3); 64 nodes/block.
// Two phases reusing one smem weight buffer to stay under 48KB static smem.
template<int DIN>
__global__ void dual_gemm_kernel(const float* __restrict__ h,
                                 const float* __restrict__ ws,
                                 const float* __restrict__ wn,
                                 float* __restrict__ s_out,
                                 float* __restrict__ t_out) {
    __shared__ float w_sh[DIN * 64];
    __shared__ float h_sh[4][DIN];
    int tid = threadIdx.x;
    int tx = tid & 63;
    int ty = tid >> 6;
    int node_base = blockIdx.x * 64;

    for (int phase = 0; phase < 2; ++phase) {
        const float* __restrict__ w   = phase ? wn    : ws;
        float* __restrict__       out = phase ? t_out : s_out;
        __syncthreads();
        for (int i = tid; i < DIN * 64; i += 256) w_sh[i] = w[i];
        __syncthreads();

        for (int it = 0; it < 16; ++it) {
            int node = node_base + it * 4 + ty;
            if (node < N_NODES) {
                for (int k = tx; k < DIN; k += 64)
                    h_sh[ty][k] = h[(size_t)node * DIN + k];
            }
            __syncthreads();
            if (node < N_NODES) {
                float acc = 0.f;
                #pragma unroll 16
                for (int k = 0; k < DIN; ++k)
                    acc = fmaf(h_sh[ty][k], w_sh[k * 64 + tx], acc);
                out[node * 64 + tx] = acc;
            }
            __syncthreads();
        }
    }
}

// ---------------- aggregate + combine + normalize ----------------
// warp per node; lane handles features (lane, lane+32)
__global__ void agg_combine_kernel(const float* __restrict__ t,
                                   const float* __restrict__ smat,
                                   float* __restrict__ hout) {
    int warp = (blockIdx.x * blockDim.x + threadIdx.x) >> 5;
    int lane = threadIdx.x & 31;
    if (warp >= N_NODES) return;

    int beg = g_rowptr[warp];
    int end = g_rowptr[warp + 1];
    float a0 = 0.f, a1 = 0.f;
    for (int i = beg; i < end; ++i) {
        int s = __ldg(&g_csr_src[i]);
        const float* tr = t + (size_t)s * 64;
        a0 += tr[lane];
        a1 += tr[lane + 32];
    }
    float id = g_invdeg[warp];
    float v0 = fmaxf(smat[warp * 64 + lane]      + a0 * id, 0.f);
    float v1 = fmaxf(smat[warp * 64 + lane + 32] + a1 * id, 0.f);

    float ss = v0 * v0 + v1 * v1;
    #pragma unroll
    for (int o = 16; o; o >>= 1) ss += __shfl_xor_sync(0xffffffffu, ss, o);
    float scale = 1.f / (sqrtf(ss) + EPS);

    hout[warp * 64 + lane]      = v0 * scale;
    hout[warp * 64 + lane + 32] = v1 * scale;
}

// ---------------- MLP head: relu(h@mw1+mb1) -> sigmoid(.@mw2+mb2) ----------------
__global__ void head_kernel(const float* __restrict__ h,
                            const float* __restrict__ mw1,
                            const float* __restrict__ mb1,
                            const float* __restrict__ mw2,
                            const float* __restrict__ mb2,
                            float* __restrict__ out) {
    __shared__ float w1s[64 * 32];
    __shared__ float b1s[32];
    __shared__ float w2s[32];
    __shared__ float b2s;

    int tid = threadIdx.x;
    for (int i = tid; i < 64 * 32; i += blockDim.x) w1s[i] = mw1[i];
    if (tid < 32) { b1s[tid] = mb1[tid]; w2s[tid] = mw2[tid]; }
    if (tid == 0) b2s = mb2[0];
    __syncthreads();

    int node = (blockIdx.x * blockDim.x + tid) >> 5;
    int lane = tid & 31;
    if (node >= N_NODES) return;

    float h0 = h[node * 64 + lane];
    float h1 = h[node * 64 + lane + 32];

    float acc = b1s[lane];
    #pragma unroll
    for (int k = 0; k < 32; ++k) {
        float hk = __shfl_sync(0xffffffffu, h0, k);
        acc = fmaf(hk, w1s[k * 32 + lane], acc);
    }
    #pragma unroll
    for (int k = 0; k < 32; ++k) {
        float hk = __shfl_sync(0xffffffffu, h1, k);
        acc = fmaf(hk, w1s[(k + 32) * 32 + lane], acc);
    }
    acc = fmaxf(acc, 0.f);

    float p = acc * w2s[lane];
    #pragma unroll
    for (int o = 16; o; o >>= 1) p += __shfl_xor_sync(0xffffffffu, p, o);

    if (lane == 0) {
        float z = p + b2s;
        out[node] = 1.f / (1.f + __expf(-z));
    }
}

// ---------------- launch ----------------
extern "C" void kernel_launch(void* const* d_in, const int* in_sizes, int n_in,
                              void* d_out, int out_size) {
    const float* x   = (const float*)d_in[0];
    const void*  ei  = (const void*)d_in[1];   // int32 or int64, detected on device
    const float* w0s = (const float*)d_in[2];
    const float* w0n = (const float*)d_in[3];
    const float* w1s = (const float*)d_in[4];
    const float* w1n = (const float*)d_in[5];
    const float* w2s = (const float*)d_in[6];
    const float* w2n = (const float*)d_in[7];
    const float* mw1 = (const float*)d_in[8];
    const float* mb1 = (const float*)d_in[9];
    const float* mw2 = (const float*)d_in[10];
    const float* mb2 = (const float*)d_in[11];
    float* out = (float*)d_out;

    float *d_s, *d_t, *d_hA, *d_hB;
    cudaGetSymbolAddress((void**)&d_s,  g_s);
    cudaGetSymbolAddress((void**)&d_t,  g_t);
    cudaGetSymbolAddress((void**)&d_hA, g_hA);
    cudaGetSymbolAddress((void**)&d_hB, g_hB);

    const int EB = (N_EDGES + 255) / 256;
    const int NB = (N_NODES + 255) / 256;
    const int GB = (N_NODES + 63) / 64;           // gemm: 64 nodes/block
    const int WB = (N_NODES * 32 + 255) / 256;    // warp-per-node kernels

    // CSR build (once per launch)
    detect_dtype_kernel<<<1, 32>>>(ei);
    zero_deg_kernel<<<NB, 256>>>();
    count_deg_kernel<<<EB, 256>>>(ei);
    scan_kernel<<<1, 1024>>>();
    fill_csr_kernel<<<EB, 256>>>(ei);

    // layer 0 (input x, DIN=128)
    dual_gemm_kernel<128><<<GB, 256>>>(x, w0s, w0n, d_s, d_t);
    agg_combine_kernel<<<WB, 256>>>(d_t, d_s, d_hA);

    // layer 1
    dual_gemm_kernel<64><<<GB, 256>>>(d_hA, w1s, w1n, d_s, d_t);
    agg_combine_kernel<<<WB, 256>>>(d_t, d_s, d_hB);

    // layer 2
    dual_gemm_kernel<64><<<GB, 256>>>(d_hB, w2s, w2n, d_s, d_t);
    agg_combine_kernel<<<WB, 256>>>(d_t, d_s, d_hA);

    // head
    head_kernel<<<WB, 256>>>(d_hA, mw1, mb1, mw2, mb2, out);
}

// round 6
// speedup vs baseline: 2.3859x; 2.3859x over previous
#include <cuda_runtime.h>
#include <cuda_bf16.h>
#include <math.h>

#define N_NODES 50000
#define N_EDGES 1600000
#define IN_DIM  128
#define HID     64
#define EPS     1e-6f

// ---------------- scratch (no allocations allowed) ----------------
__device__ int   g_is64;                 // 1 if edge_index is int64, 0 if int32
__device__ int   g_deg[N_NODES];
__device__ int   g_rowptr[N_NODES + 1];
__device__ int   g_cursor[N_NODES];
__device__ float g_invdeg[N_NODES];
__device__ int   g_csr_src[N_EDGES];

__device__ float g_s[N_NODES * HID];
__device__ float g_t[N_NODES * HID];
__device__ float g_hA[N_NODES * HID];
__device__ float g_hB[N_NODES * HID];

// ---------------- edge dtype detection (parallel) ----------------
// JAX x64-disabled silently downgrades jnp.int64 -> int32. Valid node ids are
// < 50000; interpret first 256 entries as int64 — any out-of-range => int32.
__global__ void detect_dtype_kernel(const void* __restrict__ ei) {
    const long long* p = (const long long*)ei;
    long long v = p[threadIdx.x];
    int bad = (v < 0 || v >= (long long)N_NODES) ? 1 : 0;
    int anybad = __syncthreads_or(bad);
    if (threadIdx.x == 0) g_is64 = anybad ? 0 : 1;
}

__device__ __forceinline__ int edge_at(const void* __restrict__ ei, int idx, int is64) {
    if (is64) return (int)((const long long*)ei)[idx];
    return ((const int*)ei)[idx];
}

// ---------------- CSR build ----------------
__global__ void zero_deg_kernel() {
    int i = blockIdx.x * blockDim.x + threadIdx.x;
    if (i < N_NODES) g_deg[i] = 0;
}

__global__ void count_deg_kernel(const void* __restrict__ ei) {
    int e = blockIdx.x * blockDim.x + threadIdx.x;
    int is64 = g_is64;
    if (e < N_EDGES) {
        int dst = edge_at(ei, N_EDGES + e, is64);
        atomicAdd(&g_deg[dst], 1);
    }
}

// single-block chunked scan: thread t owns a contiguous chunk; local sums are
// scanned with two-level warp shuffles, then each thread writes its prefix run.
__global__ void scan_kernel() {
    __shared__ int warp_sums[32];
    const int T = 1024;
    const int C = (N_NODES + T - 1) / T;      // 49
    int tid  = threadIdx.x;
    int lane = tid & 31, wid = tid >> 5;
    int begp = tid * C;
    int endp = min(begp + C, N_NODES);

    int local = 0;
    for (int i = begp; i < endp; ++i) local += g_deg[i];

    // inclusive scan of `local` across 1024 threads
    int v = local;
    #pragma unroll
    for (int o = 1; o < 32; o <<= 1) {
        int u = __shfl_up_sync(0xffffffffu, v, o);
        if (lane >= o) v += u;
    }
    if (lane == 31) warp_sums[wid] = v;
    __syncthreads();
    if (wid == 0) {
        int w = warp_sums[lane];
        #pragma unroll
        for (int o = 1; o < 32; o <<= 1) {
            int u = __shfl_up_sync(0xffffffffu, w, o);
            if (lane >= o) w += u;
        }
        warp_sums[lane] = w;
    }
    __syncthreads();
    int excl = (v - local) + (wid ? warp_sums[wid - 1] : 0);

    int run = excl;
    for (int i = begp; i < endp; ++i) {
        int d = g_deg[i];
        g_rowptr[i] = run;
        g_cursor[i] = run;
        g_invdeg[i] = 1.0f / (float)max(d, 1);
        run += d;
    }
    if (tid == 0) g_rowptr[N_NODES] = N_EDGES;
}

__global__ void fill_csr_kernel(const void* __restrict__ ei) {
    int e = blockIdx.x * blockDim.x + threadIdx.x;
    int is64 = g_is64;
    if (e < N_EDGES) {
        int src = edge_at(ei, e, is64);
        int dst = edge_at(ei, N_EDGES + e, is64);
        int pos = atomicAdd(&g_cursor[dst], 1);
        g_csr_src[pos] = src;
    }
}

// ---------------- fused dual GEMM: s = h@ws, t = h@wn ----------------
// Both weight matrices resident in dynamic smem; one pass over h.
// 256 threads = 32 tx (2 output cols each, float2) x 8 ty (4 nodes each).
// 64 nodes per block in 2 iterations of 32 contiguous nodes.
template<int DIN>
__global__ void dual_gemm_kernel(const float* __restrict__ h,
                                 const float* __restrict__ ws,
                                 const float* __restrict__ wn,
                                 float* __restrict__ s_out,
                                 float* __restrict__ t_out) {
    extern __shared__ float smem[];
    float* ws_sh = smem;                       // DIN*64
    float* wn_sh = smem + DIN * 64;            // DIN*64
    float* h_sh  = smem + 2 * DIN * 64;        // 32*DIN

    int tid = threadIdx.x;
    int tx  = tid & 31;
    int ty  = tid >> 5;

    // load both weight matrices (float4)
    const float4* ws4 = (const float4*)ws;
    const float4* wn4 = (const float4*)wn;
    #pragma unroll 4
    for (int i = tid; i < DIN * 16; i += 256) {
        ((float4*)ws_sh)[i] = ws4[i];
        ((float4*)wn_sh)[i] = wn4[i];
    }
    __syncthreads();

    #pragma unroll
    for (int iter = 0; iter < 2; ++iter) {
        int nb = blockIdx.x * 64 + iter * 32;
        if (nb >= N_NODES) break;
        int vn = min(32, N_NODES - nb);
        int valid_f4 = vn * (DIN / 4);

        const float4* hsrc = (const float4*)(h + (size_t)nb * DIN);
        for (int i = tid; i < 32 * (DIN / 4); i += 256)
            ((float4*)h_sh)[i] = (i < valid_f4) ? hsrc[i] : make_float4(0.f, 0.f, 0.f, 0.f);
        __syncthreads();

        int row = ty * 4;
        float2 as0 = {0,0}, as1 = {0,0}, as2 = {0,0}, as3 = {0,0};
        float2 at0 = {0,0}, at1 = {0,0}, at2 = {0,0}, at3 = {0,0};
        const float4* h0 = (const float4*)(h_sh + (row + 0) * DIN);
        const float4* h1 = (const float4*)(h_sh + (row + 1) * DIN);
        const float4* h2 = (const float4*)(h_sh + (row + 2) * DIN);
        const float4* h3 = (const float4*)(h_sh + (row + 3) * DIN);

        #pragma unroll 4
        for (int kq = 0; kq < DIN / 4; ++kq) {
            float4 v0 = h0[kq], v1 = h1[kq], v2 = h2[kq], v3 = h3[kq];
            const float* e0 = (const float*)&v0;
            const float* e1 = (const float*)&v1;
            const float* e2 = (const float*)&v2;
            const float* e3 = (const float*)&v3;
            #pragma unroll
            for (int j = 0; j < 4; ++j) {
                int k = kq * 4 + j;
                float2 wsv = *(const float2*)&ws_sh[k * 64 + 2 * tx];
                float2 wnv = *(const float2*)&wn_sh[k * 64 + 2 * tx];
                float a0 = e0[j], a1 = e1[j], a2 = e2[j], a3 = e3[j];
                as0.x = fmaf(a0, wsv.x, as0.x); as0.y = fmaf(a0, wsv.y, as0.y);
                as1.x = fmaf(a1, wsv.x, as1.x); as1.y = fmaf(a1, wsv.y, as1.y);
                as2.x = fmaf(a2, wsv.x, as2.x); as2.y = fmaf(a2, wsv.y, as2.y);
                as3.x = fmaf(a3, wsv.x, as3.x); as3.y = fmaf(a3, wsv.y, as3.y);
                at0.x = fmaf(a0, wnv.x, at0.x); at0.y = fmaf(a0, wnv.y, at0.y);
                at1.x = fmaf(a1, wnv.x, at1.x); at1.y = fmaf(a1, wnv.y, at1.y);
                at2.x = fmaf(a2, wnv.x, at2.x); at2.y = fmaf(a2, wnv.y, at2.y);
                at3.x = fmaf(a3, wnv.x, at3.x); at3.y = fmaf(a3, wnv.y, at3.y);
            }
        }

        #pragma unroll
        for (int n = 0; n < 4; ++n) {
            int node = nb + row + n;
            if (node < N_NODES) {
                float2 sv = (n == 0) ? as0 : (n == 1) ? as1 : (n == 2) ? as2 : as3;
                float2 tv = (n == 0) ? at0 : (n == 1) ? at1 : (n == 2) ? at2 : at3;
                *(float2*)&s_out[(size_t)node * 64 + 2 * tx] = sv;
                *(float2*)&t_out[(size_t)node * 64 + 2 * tx] = tv;
            }
        }
        __syncthreads();
    }
}

// ---------------- aggregate + combine + normalize ----------------
// warp per node; lane handles feature pair (2*lane, 2*lane+1) via float2
__global__ void agg_combine_kernel(const float* __restrict__ t,
                                   const float* __restrict__ smat,
                                   float* __restrict__ hout) {
    int warp = (blockIdx.x * blockDim.x + threadIdx.x) >> 5;
    int lane = threadIdx.x & 31;
    if (warp >= N_NODES) return;

    int beg = g_rowptr[warp];
    int end = g_rowptr[warp + 1];
    const float2* t2 = (const float2*)t;

    float ax = 0.f, ay = 0.f, bx = 0.f, by = 0.f;
    int i = beg;
    for (; i + 2 <= end; i += 2) {
        int s0 = __ldg(&g_csr_src[i]);
        int s1 = __ldg(&g_csr_src[i + 1]);
        float2 u = t2[(size_t)s0 * 32 + lane];
        float2 w = t2[(size_t)s1 * 32 + lane];
        ax += u.x; ay += u.y;
        bx += w.x; by += w.y;
    }
    if (i < end) {
        int s0 = __ldg(&g_csr_src[i]);
        float2 u = t2[(size_t)s0 * 32 + lane];
        ax += u.x; ay += u.y;
    }
    ax += bx; ay += by;

    float id = g_invdeg[warp];
    float2 sm = ((const float2*)smat)[(size_t)warp * 32 + lane];
    float v0 = fmaxf(sm.x + ax * id, 0.f);
    float v1 = fmaxf(sm.y + ay * id, 0.f);

    float ss = v0 * v0 + v1 * v1;
    #pragma unroll
    for (int o = 16; o; o >>= 1) ss += __shfl_xor_sync(0xffffffffu, ss, o);
    float scale = 1.f / (sqrtf(ss) + EPS);

    float2 r; r.x = v0 * scale; r.y = v1 * scale;
    ((float2*)hout)[(size_t)warp * 32 + lane] = r;
}

// ---------------- MLP head: relu(h@mw1+mb1) -> sigmoid(.@mw2+mb2) ----------------
// grid-stride over node-warps to amortize the smem weight load
__global__ void head_kernel(const float* __restrict__ h,
                            const float* __restrict__ mw1,
                            const float* __restrict__ mb1,
                            const float* __restrict__ mw2,
                            const float* __restrict__ mb2,
                            float* __restrict__ out) {
    __shared__ float w1s[64 * 32];
    __shared__ float b1s[32];
    __shared__ float w2s[32];
    __shared__ float b2s;

    int tid = threadIdx.x;
    for (int i = tid; i < 64 * 32; i += blockDim.x) w1s[i] = mw1[i];
    if (tid < 32) { b1s[tid] = mb1[tid]; w2s[tid] = mw2[tid]; }
    if (tid == 0) b2s = mb2[0];
    __syncthreads();

    int lane = tid & 31;
    int warp0 = (blockIdx.x * blockDim.x + tid) >> 5;
    int nwarps = (gridDim.x * blockDim.x) >> 5;

    for (int node = warp0; node < N_NODES; node += nwarps) {
        float h0 = h[(size_t)node * 64 + lane];
        float h1 = h[(size_t)node * 64 + lane + 32];

        float acc = b1s[lane];
        #pragma unroll
        for (int k = 0; k < 32; ++k) {
            float hk = __shfl_sync(0xffffffffu, h0, k);
            acc = fmaf(hk, w1s[k * 32 + lane], acc);
        }
        #pragma unroll
        for (int k = 0; k < 32; ++k) {
            float hk = __shfl_sync(0xffffffffu, h1, k);
            acc = fmaf(hk, w1s[(k + 32) * 32 + lane], acc);
        }
        acc = fmaxf(acc, 0.f);

        float p = acc * w2s[lane];
        #pragma unroll
        for (int o = 16; o; o >>= 1) p += __shfl_xor_sync(0xffffffffu, p, o);

        if (lane == 0) {
            float z = p + b2s;
            out[node] = 1.f / (1.f + __expf(-z));
        }
    }
}

// ---------------- launch ----------------
extern "C" void kernel_launch(void* const* d_in, const int* in_sizes, int n_in,
                              void* d_out, int out_size) {
    const float* x   = (const float*)d_in[0];
    const void*  ei  = (const void*)d_in[1];   // int32 or int64, detected on device
    const float* w0s = (const float*)d_in[2];
    const float* w0n = (const float*)d_in[3];
    const float* w1s = (const float*)d_in[4];
    const float* w1n = (const float*)d_in[5];
    const float* w2s = (const float*)d_in[6];
    const float* w2n = (const float*)d_in[7];
    const float* mw1 = (const float*)d_in[8];
    const float* mb1 = (const float*)d_in[9];
    const float* mw2 = (const float*)d_in[10];
    const float* mb2 = (const float*)d_in[11];
    float* out = (float*)d_out;

    float *d_s, *d_t, *d_hA, *d_hB;
    cudaGetSymbolAddress((void**)&d_s,  g_s);
    cudaGetSymbolAddress((void**)&d_t,  g_t);
    cudaGetSymbolAddress((void**)&d_hA, g_hA);
    cudaGetSymbolAddress((void**)&d_hB, g_hB);

    // dynamic smem: DIN*160 floats. Set attributes unconditionally every call
    // (idempotent, not a graph node) — no static guards allowed.
    const int SMEM128 = 128 * 160 * 4;   // 81920
    const int SMEM64  = 64 * 160 * 4;    // 40960
    cudaFuncSetAttribute(dual_gemm_kernel<128>,
                         cudaFuncAttributeMaxDynamicSharedMemorySize, SMEM128);
    cudaFuncSetAttribute(dual_gemm_kernel<64>,
                         cudaFuncAttributeMaxDynamicSharedMemorySize, SMEM64);

    const int EB = (N_EDGES + 255) / 256;
    const int NB = (N_NODES + 255) / 256;
    const int GB = (N_NODES + 63) / 64;           // gemm: 64 nodes/block
    const int WB = (N_NODES * 32 + 255) / 256;    // warp-per-node kernels

    // CSR build (once per launch)
    detect_dtype_kernel<<<1, 256>>>(ei);
    zero_deg_kernel<<<NB, 256>>>();
    count_deg_kernel<<<EB, 256>>>(ei);
    scan_kernel<<<1, 1024>>>();
    fill_csr_kernel<<<EB, 256>>>(ei);

    // layer 0 (input x, DIN=128)
    dual_gemm_kernel<128><<<GB, 256, SMEM128>>>(x, w0s, w0n, d_s, d_t);
    agg_combine_kernel<<<WB, 256>>>(d_t, d_s, d_hA);

    // layer 1
    dual_gemm_kernel<64><<<GB, 256, SMEM64>>>(d_hA, w1s, w1n, d_s, d_t);
    agg_combine_kernel<<<WB, 256>>>(d_t, d_s, d_hB);

    // layer 2
    dual_gemm_kernel<64><<<GB, 256, SMEM64>>>(d_hB, w2s, w2n, d_s, d_t);
    agg_combine_kernel<<<WB, 256>>>(d_t, d_s, d_hA);

    // head
    head_kernel<<<1024, 256>>>(d_hA, mw1, mb1, mw2, mb2, out);
}

// round 7
// speedup vs baseline: 2.8507x; 1.1948x over previous
#include <cuda_runtime.h>
#include <cuda_bf16.h>
#include <math.h>

#define N_NODES 50000
#define N_EDGES 1600000
#define IN_DIM  128
#define HID     64
#define EPS     1e-6f

// ---------------- scratch (no allocations allowed) ----------------
__device__ int   g_is64;                 // 1 if edge_index is int64, 0 if int32
__device__ int   g_deg[N_NODES];
__device__ int   g_rowptr[N_NODES + 1];
__device__ int   g_cursor[N_NODES];
__device__ float g_invdeg[N_NODES];
__device__ int   g_csr_src[N_EDGES];

__device__ float g_s[N_NODES * HID];
__device__ float g_t[N_NODES * HID];
__device__ float g_hA[N_NODES * HID];
__device__ float g_hB[N_NODES * HID];

// ---------------- edge dtype detection (parallel) ----------------
// JAX x64-disabled silently downgrades jnp.int64 -> int32. Valid node ids are
// < 50000; interpret first 256 entries as int64 — any out-of-range => int32.
__global__ void detect_dtype_kernel(const void* __restrict__ ei) {
    const long long* p = (const long long*)ei;
    long long v = p[threadIdx.x];
    int bad = (v < 0 || v >= (long long)N_NODES) ? 1 : 0;
    int anybad = __syncthreads_or(bad);
    if (threadIdx.x == 0) g_is64 = anybad ? 0 : 1;
}

__device__ __forceinline__ int edge_at(const void* __restrict__ ei, int idx, int is64) {
    if (is64) return (int)((const long long*)ei)[idx];
    return ((const int*)ei)[idx];
}

// ---------------- CSR build ----------------
__global__ void zero_deg_kernel() {
    int i = blockIdx.x * blockDim.x + threadIdx.x;
    if (i < N_NODES) g_deg[i] = 0;
}

__global__ void count_deg_kernel(const void* __restrict__ ei) {
    int e = blockIdx.x * blockDim.x + threadIdx.x;
    int is64 = g_is64;
    if (e < N_EDGES) {
        int dst = edge_at(ei, N_EDGES + e, is64);
        atomicAdd(&g_deg[dst], 1);
    }
}

// single-block TILE-COALESCED scan: 49 tiles of 1024 contiguous elements.
// Per tile: coalesced load, warp shuffle scan, cross-warp smem scan, coalesced
// writes. Every access has conflict/split degree 1 (vs. 32 in the chunked
// version, which serialized ~200k L1tex wavefronts through one SM).
__global__ void scan_kernel() {
    __shared__ int warp_sums[32];
    const int T = 1024;
    const int NTILES = (N_NODES + T - 1) / T;   // 49
    int tid  = threadIdx.x;
    int lane = tid & 31, wid = tid >> 5;

    int carry = 0;
    for (int tile = 0; tile < NTILES; ++tile) {
        int idx = tile * T + tid;
        int d = (idx < N_NODES) ? g_deg[idx] : 0;

        // warp inclusive scan
        int v = d;
        #pragma unroll
        for (int o = 1; o < 32; o <<= 1) {
            int u = __shfl_up_sync(0xffffffffu, v, o);
            if (lane >= o) v += u;
        }
        if (lane == 31) warp_sums[wid] = v;
        __syncthreads();
        if (wid == 0) {
            int w = warp_sums[lane];
            #pragma unroll
            for (int o = 1; o < 32; o <<= 1) {
                int u = __shfl_up_sync(0xffffffffu, w, o);
                if (lane >= o) w += u;
            }
            warp_sums[lane] = w;
        }
        __syncthreads();

        int excl = carry + (v - d) + (wid ? warp_sums[wid - 1] : 0);
        if (idx < N_NODES) {
            g_rowptr[idx] = excl;
            g_cursor[idx] = excl;
            g_invdeg[idx] = 1.0f / (float)max(d, 1);
        }
        carry += warp_sums[31];
        __syncthreads();   // protect warp_sums before next tile overwrites
    }
    if (tid == 0) g_rowptr[N_NODES] = N_EDGES;
}

__global__ void fill_csr_kernel(const void* __restrict__ ei) {
    int e = blockIdx.x * blockDim.x + threadIdx.x;
    int is64 = g_is64;
    if (e < N_EDGES) {
        int src = edge_at(ei, e, is64);
        int dst = edge_at(ei, N_EDGES + e, is64);
        int pos = atomicAdd(&g_cursor[dst], 1);
        g_csr_src[pos] = src;
    }
}

// ---------------- fused dual GEMM: s = h@ws, t = h@wn ----------------
// Both weight matrices resident in dynamic smem; one pass over h.
// 256 threads = 32 tx (2 output cols each, float2) x 8 ty (4 nodes each).
// 64 nodes per block in 2 iterations of 32 contiguous nodes.
template<int DIN>
__global__ void dual_gemm_kernel(const float* __restrict__ h,
                                 const float* __restrict__ ws,
                                 const float* __restrict__ wn,
                                 float* __restrict__ s_out,
                                 float* __restrict__ t_out) {
    extern __shared__ float smem[];
    float* ws_sh = smem;                       // DIN*64
    float* wn_sh = smem + DIN * 64;            // DIN*64
    float* h_sh  = smem + 2 * DIN * 64;        // 32*DIN

    int tid = threadIdx.x;
    int tx  = tid & 31;
    int ty  = tid >> 5;

    // load both weight matrices (float4)
    const float4* ws4 = (const float4*)ws;
    const float4* wn4 = (const float4*)wn;
    #pragma unroll 4
    for (int i = tid; i < DIN * 16; i += 256) {
        ((float4*)ws_sh)[i] = ws4[i];
        ((float4*)wn_sh)[i] = wn4[i];
    }
    __syncthreads();

    #pragma unroll
    for (int iter = 0; iter < 2; ++iter) {
        int nb = blockIdx.x * 64 + iter * 32;
        if (nb >= N_NODES) break;
        int vn = min(32, N_NODES - nb);
        int valid_f4 = vn * (DIN / 4);

        const float4* hsrc = (const float4*)(h + (size_t)nb * DIN);
        for (int i = tid; i < 32 * (DIN / 4); i += 256)
            ((float4*)h_sh)[i] = (i < valid_f4) ? hsrc[i] : make_float4(0.f, 0.f, 0.f, 0.f);
        __syncthreads();

        int row = ty * 4;
        float2 as0 = {0,0}, as1 = {0,0}, as2 = {0,0}, as3 = {0,0};
        float2 at0 = {0,0}, at1 = {0,0}, at2 = {0,0}, at3 = {0,0};
        const float4* h0 = (const float4*)(h_sh + (row + 0) * DIN);
        const float4* h1 = (const float4*)(h_sh + (row + 1) * DIN);
        const float4* h2 = (const float4*)(h_sh + (row + 2) * DIN);
        const float4* h3 = (const float4*)(h_sh + (row + 3) * DIN);

        #pragma unroll 4
        for (int kq = 0; kq < DIN / 4; ++kq) {
            float4 v0 = h0[kq], v1 = h1[kq], v2 = h2[kq], v3 = h3[kq];
            const float* e0 = (const float*)&v0;
            const float* e1 = (const float*)&v1;
            const float* e2 = (const float*)&v2;
            const float* e3 = (const float*)&v3;
            #pragma unroll
            for (int j = 0; j < 4; ++j) {
                int k = kq * 4 + j;
                float2 wsv = *(const float2*)&ws_sh[k * 64 + 2 * tx];
                float2 wnv = *(const float2*)&wn_sh[k * 64 + 2 * tx];
                float a0 = e0[j], a1 = e1[j], a2 = e2[j], a3 = e3[j];
                as0.x = fmaf(a0, wsv.x, as0.x); as0.y = fmaf(a0, wsv.y, as0.y);
                as1.x = fmaf(a1, wsv.x, as1.x); as1.y = fmaf(a1, wsv.y, as1.y);
                as2.x = fmaf(a2, wsv.x, as2.x); as2.y = fmaf(a2, wsv.y, as2.y);
                as3.x = fmaf(a3, wsv.x, as3.x); as3.y = fmaf(a3, wsv.y, as3.y);
                at0.x = fmaf(a0, wnv.x, at0.x); at0.y = fmaf(a0, wnv.y, at0.y);
                at1.x = fmaf(a1, wnv.x, at1.x); at1.y = fmaf(a1, wnv.y, at1.y);
                at2.x = fmaf(a2, wnv.x, at2.x); at2.y = fmaf(a2, wnv.y, at2.y);
                at3.x = fmaf(a3, wnv.x, at3.x); at3.y = fmaf(a3, wnv.y, at3.y);
            }
        }

        #pragma unroll
        for (int n = 0; n < 4; ++n) {
            int node = nb + row + n;
            if (node < N_NODES) {
                float2 sv = (n == 0) ? as0 : (n == 1) ? as1 : (n == 2) ? as2 : as3;
                float2 tv = (n == 0) ? at0 : (n == 1) ? at1 : (n == 2) ? at2 : at3;
                *(float2*)&s_out[(size_t)node * 64 + 2 * tx] = sv;
                *(float2*)&t_out[(size_t)node * 64 + 2 * tx] = tv;
            }
        }
        __syncthreads();
    }
}

// ---------------- aggregate + combine + normalize ----------------
// warp per node; lane handles feature pair (2*lane, 2*lane+1) via float2
__global__ void agg_combine_kernel(const float* __restrict__ t,
                                   const float* __restrict__ smat,
                                   float* __restrict__ hout) {
    int warp = (blockIdx.x * blockDim.x + threadIdx.x) >> 5;
    int lane = threadIdx.x & 31;
    if (warp >= N_NODES) return;

    int beg = g_rowptr[warp];
    int end = g_rowptr[warp + 1];
    const float2* t2 = (const float2*)t;

    float ax = 0.f, ay = 0.f, bx = 0.f, by = 0.f;
    int i = beg;
    for (; i + 2 <= end; i += 2) {
        int s0 = __ldg(&g_csr_src[i]);
        int s1 = __ldg(&g_csr_src[i + 1]);
        float2 u = t2[(size_t)s0 * 32 + lane];
        float2 w = t2[(size_t)s1 * 32 + lane];
        ax += u.x; ay += u.y;
        bx += w.x; by += w.y;
    }
    if (i < end) {
        int s0 = __ldg(&g_csr_src[i]);
        float2 u = t2[(size_t)s0 * 32 + lane];
        ax += u.x; ay += u.y;
    }
    ax += bx; ay += by;

    float id = g_invdeg[warp];
    float2 sm = ((const float2*)smat)[(size_t)warp * 32 + lane];
    float v0 = fmaxf(sm.x + ax * id, 0.f);
    float v1 = fmaxf(sm.y + ay * id, 0.f);

    float ss = v0 * v0 + v1 * v1;
    #pragma unroll
    for (int o = 16; o; o >>= 1) ss += __shfl_xor_sync(0xffffffffu, ss, o);
    float scale = 1.f / (sqrtf(ss) + EPS);

    float2 r; r.x = v0 * scale; r.y = v1 * scale;
    ((float2*)hout)[(size_t)warp * 32 + lane] = r;
}

// ---------------- MLP head: relu(h@mw1+mb1) -> sigmoid(.@mw2+mb2) ----------------
// grid-stride over node-warps to amortize the smem weight load
__global__ void head_kernel(const float* __restrict__ h,
                            const float* __restrict__ mw1,
                            const float* __restrict__ mb1,
                            const float* __restrict__ mw2,
                            const float* __restrict__ mb2,
                            float* __restrict__ out) {
    __shared__ float w1s[64 * 32];
    __shared__ float b1s[32];
    __shared__ float w2s[32];
    __shared__ float b2s;

    int tid = threadIdx.x;
    for (int i = tid; i < 64 * 32; i += blockDim.x) w1s[i] = mw1[i];
    if (tid < 32) { b1s[tid] = mb1[tid]; w2s[tid] = mw2[tid]; }
    if (tid == 0) b2s = mb2[0];
    __syncthreads();

    int lane = tid & 31;
    int warp0 = (blockIdx.x * blockDim.x + tid) >> 5;
    int nwarps = (gridDim.x * blockDim.x) >> 5;

    for (int node = warp0; node < N_NODES; node += nwarps) {
        float h0 = h[(size_t)node * 64 + lane];
        float h1 = h[(size_t)node * 64 + lane + 32];

        float acc = b1s[lane];
        #pragma unroll
        for (int k = 0; k < 32; ++k) {
            float hk = __shfl_sync(0xffffffffu, h0, k);
            acc = fmaf(hk, w1s[k * 32 + lane], acc);
        }
        #pragma unroll
        for (int k = 0; k < 32; ++k) {
            float hk = __shfl_sync(0xffffffffu, h1, k);
            acc = fmaf(hk, w1s[(k + 32) * 32 + lane], acc);
        }
        acc = fmaxf(acc, 0.f);

        float p = acc * w2s[lane];
        #pragma unroll
        for (int o = 16; o; o >>= 1) p += __shfl_xor_sync(0xffffffffu, p, o);

        if (lane == 0) {
            float z = p + b2s;
            out[node] = 1.f / (1.f + __expf(-z));
        }
    }
}

// ---------------- launch ----------------
extern "C" void kernel_launch(void* const* d_in, const int* in_sizes, int n_in,
                              void* d_out, int out_size) {
    const float* x   = (const float*)d_in[0];
    const void*  ei  = (const void*)d_in[1];   // int32 or int64, detected on device
    const float* w0s = (const float*)d_in[2];
    const float* w0n = (const float*)d_in[3];
    const float* w1s = (const float*)d_in[4];
    const float* w1n = (const float*)d_in[5];
    const float* w2s = (const float*)d_in[6];
    const float* w2n = (const float*)d_in[7];
    const float* mw1 = (const float*)d_in[8];
    const float* mb1 = (const float*)d_in[9];
    const float* mw2 = (const float*)d_in[10];
    const float* mb2 = (const float*)d_in[11];
    float* out = (float*)d_out;

    float *d_s, *d_t, *d_hA, *d_hB;
    cudaGetSymbolAddress((void**)&d_s,  g_s);
    cudaGetSymbolAddress((void**)&d_t,  g_t);
    cudaGetSymbolAddress((void**)&d_hA, g_hA);
    cudaGetSymbolAddress((void**)&d_hB, g_hB);

    // dynamic smem: DIN*160 floats. Set attributes unconditionally every call
    // (idempotent, not a graph node) — no static guards allowed.
    const int SMEM128 = 128 * 160 * 4;   // 81920
    const int SMEM64  = 64 * 160 * 4;    // 40960
    cudaFuncSetAttribute(dual_gemm_kernel<128>,
                         cudaFuncAttributeMaxDynamicSharedMemorySize, SMEM128);
    cudaFuncSetAttribute(dual_gemm_kernel<64>,
                         cudaFuncAttributeMaxDynamicSharedMemorySize, SMEM64);

    const int EB = (N_EDGES + 255) / 256;
    const int NB = (N_NODES + 255) / 256;
    const int GB = (N_NODES + 63) / 64;           // gemm: 64 nodes/block
    const int WB = (N_NODES * 32 + 255) / 256;    // warp-per-node kernels

    // CSR build (once per launch)
    detect_dtype_kernel<<<1, 256>>>(ei);
    zero_deg_kernel<<<NB, 256>>>();
    count_deg_kernel<<<EB, 256>>>(ei);
    scan_kernel<<<1, 1024>>>();
    fill_csr_kernel<<<EB, 256>>>(ei);

    // layer 0 (input x, DIN=128)
    dual_gemm_kernel<128><<<GB, 256, SMEM128>>>(x, w0s, w0n, d_s, d_t);
    agg_combine_kernel<<<WB, 256>>>(d_t, d_s, d_hA);

    // layer 1
    dual_gemm_kernel<64><<<GB, 256, SMEM64>>>(d_hA, w1s, w1n, d_s, d_t);
    agg_combine_kernel<<<WB, 256>>>(d_t, d_s, d_hB);

    // layer 2
    dual_gemm_kernel<64><<<GB, 256, SMEM64>>>(d_hB, w2s, w2n, d_s, d_t);
    agg_combine_kernel<<<WB, 256>>>(d_t, d_s, d_hA);

    // head
    head_kernel<<<1024, 256>>>(d_hA, mw1, mb1, mw2, mb2, out);
}

// round 8
// speedup vs baseline: 3.2878x; 1.1533x over previous
#include <cuda_runtime.h>
#include <cuda_bf16.h>
#include <math.h>

#define N_NODES 50000
#define N_EDGES 1600000
#define IN_DIM  128
#define HID     64
#define EPS     1e-6f

#define SCAN_T   1024
#define NTILES   ((N_NODES + SCAN_T - 1) / SCAN_T)   // 49

// ---------------- scratch (no allocations allowed) ----------------
__device__ int   g_is64;                 // 1 if edge_index is int64, 0 if int32
__device__ int   g_deg[N_NODES];
__device__ int   g_rowptr[N_NODES + 1];
__device__ int   g_cursor[N_NODES];
__device__ float g_invdeg[N_NODES];
__device__ int   g_csr_src[N_EDGES];
__device__ int   g_tile_sums[64];
__device__ int   g_tile_prefix[64];

__device__ float g_s[N_NODES * HID];
__device__ float g_t[N_NODES * HID];
__device__ float g_hA[N_NODES * HID];
__device__ float g_hB[N_NODES * HID];

// ---------------- edge dtype detection (parallel) ----------------
// JAX x64-disabled silently downgrades jnp.int64 -> int32. Valid node ids are
// < 50000; interpret first 256 entries as int64 — any out-of-range => int32.
__global__ void detect_dtype_kernel(const void* __restrict__ ei) {
    const long long* p = (const long long*)ei;
    long long v = p[threadIdx.x];
    int bad = (v < 0 || v >= (long long)N_NODES) ? 1 : 0;
    int anybad = __syncthreads_or(bad);
    if (threadIdx.x == 0) g_is64 = anybad ? 0 : 1;
}

__device__ __forceinline__ int edge_at(const void* __restrict__ ei, int idx, int is64) {
    if (is64) return (int)((const long long*)ei)[idx];
    return ((const int*)ei)[idx];
}

// ---------------- CSR build ----------------
__global__ void zero_deg_kernel() {
    int i = blockIdx.x * blockDim.x + threadIdx.x;
    if (i < N_NODES) g_deg[i] = 0;
}

__global__ void count_deg_kernel(const void* __restrict__ ei) {
    int e = blockIdx.x * blockDim.x + threadIdx.x;
    int is64 = g_is64;
    if (e < N_EDGES) {
        int dst = edge_at(ei, N_EDGES + e, is64);
        atomicAdd(&g_deg[dst], 1);
    }
}

// ---- decoupled 3-phase scan (parallel across SMs, no serial carry chain) ----

// phase 1: per-tile sums. 49 blocks x 256 threads, 4 elems/thread, coalesced.
__global__ void tile_sum_kernel() {
    __shared__ int wsum[8];
    int b = blockIdx.x, tid = threadIdx.x;
    int base = b * SCAN_T;
    int s = 0;
    #pragma unroll
    for (int i = 0; i < 4; ++i) {
        int idx = base + tid + i * 256;
        if (idx < N_NODES) s += g_deg[idx];
    }
    #pragma unroll
    for (int o = 16; o; o >>= 1) s += __shfl_xor_sync(0xffffffffu, s, o);
    if ((tid & 31) == 0) wsum[tid >> 5] = s;
    __syncthreads();
    if (tid < 8) {
        int v = wsum[tid];
        #pragma unroll
        for (int o = 4; o; o >>= 1) v += __shfl_xor_sync(0xffu, v, o);
        if (tid == 0) g_tile_sums[b] = v;
    }
}

// phase 2: exclusive scan of 49 tile sums (one tiny block).
__global__ void tile_scan_kernel() {
    __shared__ int sh[64];
    int tid = threadIdx.x;
    int v = (tid < NTILES) ? g_tile_sums[tid] : 0;
    sh[tid] = v;
    __syncthreads();
    for (int o = 1; o < 64; o <<= 1) {
        int add = (tid >= o) ? sh[tid - o] : 0;
        __syncthreads();
        sh[tid] += add;
        __syncthreads();
    }
    if (tid < NTILES) g_tile_prefix[tid] = sh[tid] - v;
}

// phase 3: independent intra-tile scans. 49 blocks x 1024 threads.
__global__ void rowptr_kernel() {
    __shared__ int warp_sums[32];
    int b = blockIdx.x, tid = threadIdx.x;
    int lane = tid & 31, wid = tid >> 5;
    int idx = b * SCAN_T + tid;
    int d = (idx < N_NODES) ? g_deg[idx] : 0;

    int v = d;
    #pragma unroll
    for (int o = 1; o < 32; o <<= 1) {
        int u = __shfl_up_sync(0xffffffffu, v, o);
        if (lane >= o) v += u;
    }
    if (lane == 31) warp_sums[wid] = v;
    __syncthreads();
    if (wid == 0) {
        int w = warp_sums[lane];
        #pragma unroll
        for (int o = 1; o < 32; o <<= 1) {
            int u = __shfl_up_sync(0xffffffffu, w, o);
            if (lane >= o) w += u;
        }
        warp_sums[lane] = w;
    }
    __syncthreads();

    if (idx < N_NODES) {
        int excl = g_tile_prefix[b] + (v - d) + (wid ? warp_sums[wid - 1] : 0);
        g_rowptr[idx] = excl;
        g_cursor[idx] = excl;
        g_invdeg[idx] = 1.0f / (float)max(d, 1);
    }
    if (b == 0 && tid == 0) g_rowptr[N_NODES] = N_EDGES;
}

__global__ void fill_csr_kernel(const void* __restrict__ ei) {
    int e = blockIdx.x * blockDim.x + threadIdx.x;
    int is64 = g_is64;
    if (e < N_EDGES) {
        int src = edge_at(ei, e, is64);
        int dst = edge_at(ei, N_EDGES + e, is64);
        int pos = atomicAdd(&g_cursor[dst], 1);
        g_csr_src[pos] = src;
    }
}

// ---------------- fused dual GEMM: s = h@ws, t = h@wn ----------------
// Both weight matrices resident in dynamic smem; one pass over h.
// 256 threads = 32 tx (2 output cols each, float2) x 8 ty (4 nodes each).
// 64 nodes per block in 2 iterations of 32 contiguous nodes.
template<int DIN>
__global__ void dual_gemm_kernel(const float* __restrict__ h,
                                 const float* __restrict__ ws,
                                 const float* __restrict__ wn,
                                 float* __restrict__ s_out,
                                 float* __restrict__ t_out) {
    extern __shared__ float smem[];
    float* ws_sh = smem;                       // DIN*64
    float* wn_sh = smem + DIN * 64;            // DIN*64
    float* h_sh  = smem + 2 * DIN * 64;        // 32*DIN

    int tid = threadIdx.x;
    int tx  = tid & 31;
    int ty  = tid >> 5;

    // load both weight matrices (float4)
    const float4* ws4 = (const float4*)ws;
    const float4* wn4 = (const float4*)wn;
    #pragma unroll 4
    for (int i = tid; i < DIN * 16; i += 256) {
        ((float4*)ws_sh)[i] = ws4[i];
        ((float4*)wn_sh)[i] = wn4[i];
    }
    __syncthreads();

    #pragma unroll
    for (int iter = 0; iter < 2; ++iter) {
        int nb = blockIdx.x * 64 + iter * 32;
        if (nb >= N_NODES) break;
        int vn = min(32, N_NODES - nb);
        int valid_f4 = vn * (DIN / 4);

        const float4* hsrc = (const float4*)(h + (size_t)nb * DIN);
        for (int i = tid; i < 32 * (DIN / 4); i += 256)
            ((float4*)h_sh)[i] = (i < valid_f4) ? hsrc[i] : make_float4(0.f, 0.f, 0.f, 0.f);
        __syncthreads();

        int row = ty * 4;
        float2 as0 = {0,0}, as1 = {0,0}, as2 = {0,0}, as3 = {0,0};
        float2 at0 = {0,0}, at1 = {0,0}, at2 = {0,0}, at3 = {0,0};
        const float4* h0 = (const float4*)(h_sh + (row + 0) * DIN);
        const float4* h1 = (const float4*)(h_sh + (row + 1) * DIN);
        const float4* h2 = (const float4*)(h_sh + (row + 2) * DIN);
        const float4* h3 = (const float4*)(h_sh + (row + 3) * DIN);

        #pragma unroll 4
        for (int kq = 0; kq < DIN / 4; ++kq) {
            float4 v0 = h0[kq], v1 = h1[kq], v2 = h2[kq], v3 = h3[kq];
            const float* e0 = (const float*)&v0;
            const float* e1 = (const float*)&v1;
            const float* e2 = (const float*)&v2;
            const float* e3 = (const float*)&v3;
            #pragma unroll
            for (int j = 0; j < 4; ++j) {
                int k = kq * 4 + j;
                float2 wsv = *(const float2*)&ws_sh[k * 64 + 2 * tx];
                float2 wnv = *(const float2*)&wn_sh[k * 64 + 2 * tx];
                float a0 = e0[j], a1 = e1[j], a2 = e2[j], a3 = e3[j];
                as0.x = fmaf(a0, wsv.x, as0.x); as0.y = fmaf(a0, wsv.y, as0.y);
                as1.x = fmaf(a1, wsv.x, as1.x); as1.y = fmaf(a1, wsv.y, as1.y);
                as2.x = fmaf(a2, wsv.x, as2.x); as2.y = fmaf(a2, wsv.y, as2.y);
                as3.x = fmaf(a3, wsv.x, as3.x); as3.y = fmaf(a3, wsv.y, as3.y);
                at0.x = fmaf(a0, wnv.x, at0.x); at0.y = fmaf(a0, wnv.y, at0.y);
                at1.x = fmaf(a1, wnv.x, at1.x); at1.y = fmaf(a1, wnv.y, at1.y);
                at2.x = fmaf(a2, wnv.x, at2.x); at2.y = fmaf(a2, wnv.y, at2.y);
                at3.x = fmaf(a3, wnv.x, at3.x); at3.y = fmaf(a3, wnv.y, at3.y);
            }
        }

        #pragma unroll
        for (int n = 0; n < 4; ++n) {
            int node = nb + row + n;
            if (node < N_NODES) {
                float2 sv = (n == 0) ? as0 : (n == 1) ? as1 : (n == 2) ? as2 : as3;
                float2 tv = (n == 0) ? at0 : (n == 1) ? at1 : (n == 2) ? at2 : at3;
                *(float2*)&s_out[(size_t)node * 64 + 2 * tx] = sv;
                *(float2*)&t_out[(size_t)node * 64 + 2 * tx] = tv;
            }
        }
        __syncthreads();
    }
}

// ---------------- aggregate + combine + normalize ----------------
// warp per node; lane handles feature pair (2*lane, 2*lane+1) via float2
__global__ void agg_combine_kernel(const float* __restrict__ t,
                                   const float* __restrict__ smat,
                                   float* __restrict__ hout) {
    int warp = (blockIdx.x * blockDim.x + threadIdx.x) >> 5;
    int lane = threadIdx.x & 31;
    if (warp >= N_NODES) return;

    int beg = g_rowptr[warp];
    int end = g_rowptr[warp + 1];
    const float2* t2 = (const float2*)t;

    float ax = 0.f, ay = 0.f, bx = 0.f, by = 0.f;
    int i = beg;
    for (; i + 2 <= end; i += 2) {
        int s0 = __ldg(&g_csr_src[i]);
        int s1 = __ldg(&g_csr_src[i + 1]);
        float2 u = t2[(size_t)s0 * 32 + lane];
        float2 w = t2[(size_t)s1 * 32 + lane];
        ax += u.x; ay += u.y;
        bx += w.x; by += w.y;
    }
    if (i < end) {
        int s0 = __ldg(&g_csr_src[i]);
        float2 u = t2[(size_t)s0 * 32 + lane];
        ax += u.x; ay += u.y;
    }
    ax += bx; ay += by;

    float id = g_invdeg[warp];
    float2 sm = ((const float2*)smat)[(size_t)warp * 32 + lane];
    float v0 = fmaxf(sm.x + ax * id, 0.f);
    float v1 = fmaxf(sm.y + ay * id, 0.f);

    float ss = v0 * v0 + v1 * v1;
    #pragma unroll
    for (int o = 16; o; o >>= 1) ss += __shfl_xor_sync(0xffffffffu, ss, o);
    float scale = 1.f / (sqrtf(ss) + EPS);

    float2 r; r.x = v0 * scale; r.y = v1 * scale;
    ((float2*)hout)[(size_t)warp * 32 + lane] = r;
}

// ---------------- MLP head: relu(h@mw1+mb1) -> sigmoid(.@mw2+mb2) ----------------
// grid-stride over node-warps to amortize the smem weight load
__global__ void head_kernel(const float* __restrict__ h,
                            const float* __restrict__ mw1,
                            const float* __restrict__ mb1,
                            const float* __restrict__ mw2,
                            const float* __restrict__ mb2,
                            float* __restrict__ out) {
    __shared__ float w1s[64 * 32];
    __shared__ float b1s[32];
    __shared__ float w2s[32];
    __shared__ float b2s;

    int tid = threadIdx.x;
    for (int i = tid; i < 64 * 32; i += blockDim.x) w1s[i] = mw1[i];
    if (tid < 32) { b1s[tid] = mb1[tid]; w2s[tid] = mw2[tid]; }
    if (tid == 0) b2s = mb2[0];
    __syncthreads();

    int lane = tid & 31;
    int warp0 = (blockIdx.x * blockDim.x + tid) >> 5;
    int nwarps = (gridDim.x * blockDim.x) >> 5;

    for (int node = warp0; node < N_NODES; node += nwarps) {
        float h0 = h[(size_t)node * 64 + lane];
        float h1 = h[(size_t)node * 64 + lane + 32];

        float acc = b1s[lane];
        #pragma unroll
        for (int k = 0; k < 32; ++k) {
            float hk = __shfl_sync(0xffffffffu, h0, k);
            acc = fmaf(hk, w1s[k * 32 + lane], acc);
        }
        #pragma unroll
        for (int k = 0; k < 32; ++k) {
            float hk = __shfl_sync(0xffffffffu, h1, k);
            acc = fmaf(hk, w1s[(k + 32) * 32 + lane], acc);
        }
        acc = fmaxf(acc, 0.f);

        float p = acc * w2s[lane];
        #pragma unroll
        for (int o = 16; o; o >>= 1) p += __shfl_xor_sync(0xffffffffu, p, o);

        if (lane == 0) {
            float z = p + b2s;
            out[node] = 1.f / (1.f + __expf(-z));
        }
    }
}

// ---------------- launch ----------------
extern "C" void kernel_launch(void* const* d_in, const int* in_sizes, int n_in,
                              void* d_out, int out_size) {
    const float* x   = (const float*)d_in[0];
    const void*  ei  = (const void*)d_in[1];   // int32 or int64, detected on device
    const float* w0s = (const float*)d_in[2];
    const float* w0n = (const float*)d_in[3];
    const float* w1s = (const float*)d_in[4];
    const float* w1n = (const float*)d_in[5];
    const float* w2s = (const float*)d_in[6];
    const float* w2n = (const float*)d_in[7];
    const float* mw1 = (const float*)d_in[8];
    const float* mb1 = (const float*)d_in[9];
    const float* mw2 = (const float*)d_in[10];
    const float* mb2 = (const float*)d_in[11];
    float* out = (float*)d_out;

    float *d_s, *d_t, *d_hA, *d_hB;
    cudaGetSymbolAddress((void**)&d_s,  g_s);
    cudaGetSymbolAddress((void**)&d_t,  g_t);
    cudaGetSymbolAddress((void**)&d_hA, g_hA);
    cudaGetSymbolAddress((void**)&d_hB, g_hB);

    // dynamic smem: DIN*160 floats. Set attributes unconditionally every call
    // (idempotent, not a graph node) — no static guards allowed.
    const int SMEM128 = 128 * 160 * 4;   // 81920
    const int SMEM64  = 64 * 160 * 4;    // 40960
    cudaFuncSetAttribute(dual_gemm_kernel<128>,
                         cudaFuncAttributeMaxDynamicSharedMemorySize, SMEM128);
    cudaFuncSetAttribute(dual_gemm_kernel<64>,
                         cudaFuncAttributeMaxDynamicSharedMemorySize, SMEM64);

    const int EB = (N_EDGES + 255) / 256;
    const int NB = (N_NODES + 255) / 256;
    const int GB = (N_NODES + 63) / 64;           // gemm: 64 nodes/block
    const int WB = (N_NODES * 32 + 255) / 256;    // warp-per-node kernels

    // CSR build (once per launch) — decoupled parallel scan
    detect_dtype_kernel<<<1, 256>>>(ei);
    zero_deg_kernel<<<NB, 256>>>();
    count_deg_kernel<<<EB, 256>>>(ei);
    tile_sum_kernel<<<NTILES, 256>>>();
    tile_scan_kernel<<<1, 64>>>();
    rowptr_kernel<<<NTILES, 1024>>>();
    fill_csr_kernel<<<EB, 256>>>(ei);

    // layer 0 (input x, DIN=128)
    dual_gemm_kernel<128><<<GB, 256, SMEM128>>>(x, w0s, w0n, d_s, d_t);
    agg_combine_kernel<<<WB, 256>>>(d_t, d_s, d_hA);

    // layer 1
    dual_gemm_kernel<64><<<GB, 256, SMEM64>>>(d_hA, w1s, w1n, d_s, d_t);
    agg_combine_kernel<<<WB, 256>>>(d_t, d_s, d_hB);

    // layer 2
    dual_gemm_kernel<64><<<GB, 256, SMEM64>>>(d_hB, w2s, w2n, d_s, d_t);
    agg_combine_kernel<<<WB, 256>>>(d_t, d_s, d_hA);

    // head
    head_kernel<<<1024, 256>>>(d_hA, mw1, mb1, mw2, mb2, out);
}